// round 1
// baseline (speedup 1.0000x reference)
#include <cuda_runtime.h>
#include <cstdint>

#define Bb 512
#define Ss 128
#define Kk 4
#define Hh 128
#define KH 512          // K*H
#define ROUT 3
#define EPSQ 1e-9f

// ---------------- scratch (device globals; no allocation allowed) ----------
__device__ float g_hat[(size_t)Bb * Kk * Ss * Hh];   // 134 MB: hat[b][k][s][h]
__device__ float g_cw[(size_t)Bb * Kk * Ss];         // 1 MB:  capsule_weight[b][k][s]
__device__ float g_denom[Kk * Ss];                   // 1/sum_b exp(cw[b,k,s])

// ---------------- GEMM: hat[b,k,s,h] = sum_h' item[b,s,h'] * w[s, k*H+h, h']
// Per-s GEMM: [B x H] @ [H x KH]^T.  Tile 64(b) x 64(d), k-chunk 64.
#define BM 64
#define BN 64
#define BKc 64

__global__ void __launch_bounds__(256) gemm_kernel(const float* __restrict__ item,
                                                   const float* __restrict__ w) {
    __shared__ float As[BKc][BM];   // k-major
    __shared__ float Bs[BKc][BN];

    const int s  = blockIdx.z;
    const int b0 = blockIdx.y * BM;
    const int d0 = blockIdx.x * BN;
    const int tid = threadIdx.x;
    const int tx = tid & 15;        // n micro-col group
    const int ty = tid >> 4;        // m micro-row group

    // load mapping: each thread owns one k-vec (4 consecutive k) across 4 rows
    const int m0 = tid & 15;
    const int kv = tid >> 4;        // 0..15  -> k = kv*4 .. kv*4+3

    const float* Ag = item + ((size_t)b0 * Ss + s) * Hh;   // row m: + m*S*H
    const float* Bg = w    + ((size_t)s * KH + d0) * Hh;   // row n: + n*H

    float acc[4][4] = {};

    #pragma unroll
    for (int kc = 0; kc < Hh; kc += BKc) {
        // ---- stage A (transpose to k-major; 2-way STS conflicts only)
        #pragma unroll
        for (int i = 0; i < 4; i++) {
            int m = m0 + 16 * i;
            float4 v = *(const float4*)(Ag + (size_t)m * (Ss * Hh) + kc + kv * 4);
            As[kv*4+0][m] = v.x; As[kv*4+1][m] = v.y;
            As[kv*4+2][m] = v.z; As[kv*4+3][m] = v.w;
        }
        // ---- stage B
        #pragma unroll
        for (int i = 0; i < 4; i++) {
            int n = m0 + 16 * i;
            float4 v = *(const float4*)(Bg + (size_t)n * Hh + kc + kv * 4);
            Bs[kv*4+0][n] = v.x; Bs[kv*4+1][n] = v.y;
            Bs[kv*4+2][n] = v.z; Bs[kv*4+3][n] = v.w;
        }
        __syncthreads();

        #pragma unroll
        for (int kk = 0; kk < BKc; kk++) {
            float4 a = *(const float4*)&As[kk][ty * 4];
            float4 b = *(const float4*)&Bs[kk][tx * 4];
            acc[0][0] += a.x * b.x; acc[0][1] += a.x * b.y; acc[0][2] += a.x * b.z; acc[0][3] += a.x * b.w;
            acc[1][0] += a.y * b.x; acc[1][1] += a.y * b.y; acc[1][2] += a.y * b.z; acc[1][3] += a.y * b.w;
            acc[2][0] += a.z * b.x; acc[2][1] += a.z * b.y; acc[2][2] += a.z * b.z; acc[2][3] += a.z * b.w;
            acc[3][0] += a.w * b.x; acc[3][1] += a.w * b.y; acc[3][2] += a.w * b.z; acc[3][3] += a.w * b.w;
        }
        __syncthreads();
    }

    // write: d = d0 + tx*4 + j ; 64-wide tiles never cross an H=128 boundary
    const int kcap = d0 >> 7;
    const int h0   = (d0 & 127) + tx * 4;
    #pragma unroll
    for (int i = 0; i < 4; i++) {
        int b = b0 + ty * 4 + i;
        float4 v = make_float4(acc[i][0], acc[i][1], acc[i][2], acc[i][3]);
        *(float4*)&g_hat[(((size_t)b * Kk + kcap) * Ss + s) * Hh + h0] = v;
    }
}

// ---------------- denom: g_denom[e] = 1 / sum_b exp(cw[b, e]),  e in [0, K*S)
__global__ void denom_kernel() {
    int e = blockIdx.x * blockDim.x + threadIdx.x;
    if (e < Kk * Ss) {
        float acc = 0.f;
        #pragma unroll 8
        for (int b = 0; b < Bb; b++)
            acc += __expf(g_cw[(size_t)b * (Kk * Ss) + e]);   // coalesced across e
        g_denom[e] = 1.0f / acc;
    }
}

// ---------------- fused routing step for one (b,k):
// sw -> cap = sw . hat -> squash -> (delta -> cw)  or  (write output)
#define PADH 132   // 128 + 4: float4-aligned rows, conflict-free access patterns

__global__ void __launch_bounds__(256) routing_kernel(const float* __restrict__ mask,
                                                      float* __restrict__ out,
                                                      int iter) {
    extern __shared__ float sm[];
    float* hat_s = sm;                        // [S][PADH]
    float* sw    = sm + Ss * PADH;            // [S]
    float* cap   = sw + Ss;                   // [H]
    float* red   = cap + Hh;                  // [128] scratch

    const int bx  = blockIdx.x;               // b*K + k
    const int b   = bx >> 2;
    const int k   = bx & 3;
    const int tid = threadIdx.x;

    // ---- stage hat tile [128 x 128] (16384 floats, contiguous in gmem)
    const float* hp = g_hat + (size_t)bx * (Ss * Hh);
    #pragma unroll
    for (int i = tid; i < (Ss * Hh) / 4; i += 256) {
        float4 v = ((const float4*)hp)[i];
        int el = i << 2;
        int s  = el >> 7;
        int h  = el & 127;
        *(float4*)&hat_s[s * PADH + h] = v;
    }

    // ---- sw[s]
    if (tid < Ss) {
        int s = tid;
        float m = mask[b * Ss + s];
        float v;
        if (iter == 0) {
            v = 1.0f / (float)Bb;             // softmax over axis-0 of zeros
        } else {
            v = __expf(g_cw[(size_t)bx * Ss + s]) * g_denom[k * Ss + s];
        }
        sw[s] = (m == 0.0f) ? 0.0f : v;
    }
    __syncthreads();

    // ---- cap[h] = sum_s sw[s] * hat[s][h]   (two s-halves across 256 threads)
    {
        int h = tid & 127;
        int half = tid >> 7;
        float acc = 0.f;
        int s0 = half * 64;
        #pragma unroll 8
        for (int s = s0; s < s0 + 64; s++)
            acc += sw[s] * hat_s[s * PADH + h];
        if (half) red[h] = acc;
        __syncthreads();
        if (!half) cap[h] = acc + red[h];
    }
    __syncthreads();

    // ---- squash: n = sum cap^2; f = n/(1+n)/sqrt(n+eps)
    {
        float v = (tid < Hh) ? cap[tid] * cap[tid] : 0.f;
        #pragma unroll
        for (int off = 16; off; off >>= 1)
            v += __shfl_down_sync(0xffffffffu, v, off);
        if ((tid & 31) == 0) red[tid >> 5] = v;   // 8 warp partials
        __syncthreads();
        if (tid == 0) {
            float n = 0.f;
            #pragma unroll
            for (int i = 0; i < 8; i++) n += red[i];
            red[8] = n / (1.0f + n) * rsqrtf(n + EPSQ);
        }
        __syncthreads();
        float f = red[8];
        if (tid < Hh) cap[tid] *= f;
    }
    __syncthreads();

    if (iter < 2) {
        // ---- delta[s] = sum_h hat[s][h]*cap[h];  cw update (write on iter 0)
        int warp = tid >> 5, lane = tid & 31;
        for (int s = warp; s < Ss; s += 8) {
            float d = 0.f;
            #pragma unroll
            for (int i = 0; i < 4; i++)
                d += hat_s[s * PADH + lane + 32 * i] * cap[lane + 32 * i];
            #pragma unroll
            for (int off = 16; off; off >>= 1)
                d += __shfl_down_sync(0xffffffffu, d, off);
            if (lane == 0) {
                size_t idx = (size_t)bx * Ss + s;
                g_cw[idx] = (iter == 0) ? d : (g_cw[idx] + d);
            }
        }
    } else {
        if (tid < Hh) out[(size_t)bx * Hh + tid] = cap[tid];
    }
}

// ---------------- launch -----------------------------------------------------
#define RSMEM ((Ss * PADH + Ss + Hh + 128) * (int)sizeof(float))   // ~69 KB

extern "C" void kernel_launch(void* const* d_in, const int* in_sizes, int n_in,
                              void* d_out, int out_size) {
    const float* item = (const float*)d_in[0];   // [B,S,H]
    const float* mask = (const float*)d_in[1];   // [B,S]
    const float* w    = (const float*)d_in[2];   // [1,S,K*H,H]
    float* out = (float*)d_out;                  // [B,K,H]

    cudaFuncSetAttribute(routing_kernel,
                         cudaFuncAttributeMaxDynamicSharedMemorySize, RSMEM);

    dim3 gg(KH / BN, Bb / BM, Ss);
    gemm_kernel<<<gg, 256>>>(item, w);

    routing_kernel<<<Bb * Kk, 256, RSMEM>>>(mask, out, 0);
    denom_kernel<<<2, 256>>>();
    routing_kernel<<<Bb * Kk, 256, RSMEM>>>(mask, out, 1);
    denom_kernel<<<2, 256>>>();
    routing_kernel<<<Bb * Kk, 256, RSMEM>>>(mask, out, 2);
}